// round 12
// baseline (speedup 1.0000x reference)
#include <cuda_runtime.h>
#include <cuda_bf16.h>
#include <cstdint>

// Problem constants (fixed by reference setup_inputs)
#define BATCH 4096
#define CELL  400
#define CELL4 100    // CELL/4
#define KMIX  10
#define TLEN  256
#define VDIM  80
#define NT    320    // 10 warps == KMIX warps
#define JPRE  4      // first 4 of 16 t-chunks prefetched to smem (t = 0..63)
#define PRE_F4 (JPRE * 16 * 20)   // 1280 float4s = 20 KB

// Dynamic smem pad: static ~26.7KB + 22KB -> ~48.7KB/CTA -> exactly 4 CTAs/SM.
// Requires cudaFuncSetAttribute opt-in (static+dynamic > 48KB default limit).
#define SMEM_PAD_BYTES (22 * 1024)

#define CP_ASYNC_16(smem_u32, gptr) \
    asm volatile("cp.async.cg.shared.global [%0], [%1], 16;" :: "r"(smem_u32), "l"(gptr))
#define CP_ASYNC_COMMIT()   asm volatile("cp.async.commit_group;" ::: "memory")
#define CP_ASYNC_WAIT_ALL() asm volatile("cp.async.wait_group 0;" ::: "memory")

__global__ __launch_bounds__(NT)
void window_fused(const float* __restrict__ x,
                  const float* __restrict__ kappa_old,
                  const float* __restrict__ onehots,
                  const float* __restrict__ W,
                  const float* __restrict__ bias,
                  float* __restrict__ out_weight,   // [B, V]
                  float* __restrict__ out_kappa)    // [B, K]
{
    const int b    = blockIdx.x;
    const int tid  = threadIdx.x;
    const int warp = tid >> 5;
    const int lane = tid & 31;

    __shared__ float4 soh[PRE_F4];      // first 64 t-rows of onehots[b]
    __shared__ float  sal[KMIX], sbe[KMIX], ska[KMIX];
    __shared__ float  sphi[TLEN];
    __shared__ float4 wpart[16 * 20];

    const float4* oh = (const float4*)(onehots + (size_t)b * TLEN * VDIM);

    // ---- issue async prefetch of first 20KB of onehots[b] (fills during prologue)
    {
        uint32_t soh_u32 = (uint32_t)__cvta_generic_to_shared(soh);
        #pragma unroll
        for (int k = 0; k < PRE_F4 / NT; k++) {
            const int i = tid + k * NT;
            CP_ASYNC_16(soh_u32 + i * 16, oh + i);
        }
        CP_ASYNC_COMMIT();
    }

    // ---- mat-vec + transforms: warp w owns mixture component w ----
    // x[b] read as warp-broadcast LDG (L1-cached across warps); W coalesced, L2-hot.
    {
        const float4* x4 = (const float4*)(x + (size_t)b * CELL);
        const float4* W4 = (const float4*)W;
        float s0 = 0.f, s1 = 0.f, s2 = 0.f;
        #pragma unroll 4
        for (int c4 = lane; c4 < CELL4; c4 += 32) {
            const float4 xv = x4[c4];
            const float4 w0 = W4[(warp)          * CELL4 + c4];
            const float4 w1 = W4[(warp + KMIX)   * CELL4 + c4];
            const float4 w2 = W4[(warp + 2*KMIX) * CELL4 + c4];
            s0 += xv.x * w0.x + xv.y * w0.y + xv.z * w0.z + xv.w * w0.w;
            s1 += xv.x * w1.x + xv.y * w1.y + xv.z * w1.z + xv.w * w1.w;
            s2 += xv.x * w2.x + xv.y * w2.y + xv.z * w2.z + xv.w * w2.w;
        }
        #pragma unroll
        for (int off = 16; off > 0; off >>= 1) {
            s0 += __shfl_xor_sync(0xffffffffu, s0, off);
            s1 += __shfl_xor_sync(0xffffffffu, s1, off);
            s2 += __shfl_xor_sync(0xffffffffu, s2, off);
        }
        if (lane == 0) {
            const float alpha = __expf(s0 + bias[warp]);
            const float beta  = __expf(s1 + bias[warp + KMIX]);
            const float kap   = kappa_old[(size_t)b * KMIX + warp]
                              + __expf(s2 + bias[warp + 2*KMIX]);
            sal[warp] = alpha;
            sbe[warp] = beta;
            ska[warp] = kap;
            out_kappa[(size_t)b * KMIX + warp] = kap;
        }
    }
    __syncthreads();

    // ---- phi[t] ----
    if (tid < TLEN) {
        const float u = (float)tid;
        float s = 0.0f;
        #pragma unroll
        for (int k = 0; k < KMIX; k++) {
            const float d = ska[k] - u;
            s += sal[k] * __expf(-sbe[k] * d * d);
        }
        sphi[tid] = s;
    }
    CP_ASYNC_WAIT_ALL();
    __syncthreads();

    // ---- streaming einsum: j<JPRE from smem, rest from global (proven shape) ----
    const int c  = tid % 20;    // float4 column (v/4)
    const int t0 = tid / 20;    // 0..15

    float4 acc = make_float4(0.f, 0.f, 0.f, 0.f);
    #pragma unroll
    for (int j = 0; j < JPRE; j++) {
        const int t = t0 + j * 16;
        const float  p = sphi[t];
        const float4 o = soh[t * 20 + c];
        acc.x += p * o.x; acc.y += p * o.y; acc.z += p * o.z; acc.w += p * o.w;
    }
    #pragma unroll
    for (int j = JPRE; j < 16; j++) {
        const int t = t0 + j * 16;
        const float  p = sphi[t];
        const float4 o = oh[t * 20 + c];
        acc.x += p * o.x; acc.y += p * o.y; acc.z += p * o.z; acc.w += p * o.w;
    }
    wpart[t0 * 20 + c] = acc;
    __syncthreads();

    if (tid < VDIM) {
        const float* wp = (const float*)wpart;
        float s = 0.0f;
        #pragma unroll
        for (int j = 0; j < 16; j++) s += wp[j * VDIM + tid];
        out_weight[(size_t)b * VDIM + tid] = s;
    }
}

extern "C" void kernel_launch(void* const* d_in, const int* in_sizes, int n_in,
                              void* d_out, int out_size)
{
    const float* x         = (const float*)d_in[0];   // [B, CELL]
    const float* kappa_old = (const float*)d_in[1];   // [B, K]
    const float* onehots   = (const float*)d_in[2];   // [B, T, V]
    const float* W         = (const float*)d_in[3];   // [3K, CELL]
    const float* bias      = (const float*)d_in[4];   // [3K]

    float* out_weight = (float*)d_out;                        // [B, V]
    float* out_kappa  = (float*)d_out + (size_t)BATCH * VDIM; // [B, K]

    // Opt in to static+dynamic > 48KB (host-side attribute set; capture-safe,
    // proven in rounds 3-7). 22KB pad -> ~48.7KB/CTA -> 4 CTAs/SM.
    cudaFuncSetAttribute(window_fused,
                         cudaFuncAttributeMaxDynamicSharedMemorySize, SMEM_PAD_BYTES);

    window_fused<<<BATCH, NT, SMEM_PAD_BYTES>>>(x, kappa_old, onehots, W, bias,
                                                out_weight, out_kappa);
}

// round 13
// speedup vs baseline: 1.3840x; 1.3840x over previous
#include <cuda_runtime.h>
#include <cuda_bf16.h>
#include <cstdint>

// Problem constants (fixed by reference setup_inputs)
#define BATCH 4096
#define CELL  400
#define CELL4 100    // CELL/4
#define KMIX  10
#define TLEN  256
#define VDIM  80
#define NT    320    // 10 warps == KMIX warps

// Streaming pipeline: 8 chunks of 32 t-rows (10KB each), 2 smem stages.
#define CHUNK_ROWS 32
#define CHUNK_F4   (CHUNK_ROWS * 20)   // 640 float4 = 10KB
#define NCHUNK     (TLEN / CHUNK_ROWS) // 8

#define CP_ASYNC_16(smem_u32, gptr) \
    asm volatile("cp.async.cg.shared.global [%0], [%1], 16;" :: "r"(smem_u32), "l"(gptr))
#define CP_ASYNC_COMMIT()  asm volatile("cp.async.commit_group;" ::: "memory")
#define CP_ASYNC_WAIT_1()  asm volatile("cp.async.wait_group 1;" ::: "memory")
#define CP_ASYNC_WAIT_0()  asm volatile("cp.async.wait_group 0;" ::: "memory")

__global__ __launch_bounds__(NT, 6)
void window_fused(const float* __restrict__ x,
                  const float* __restrict__ kappa_old,
                  const float* __restrict__ onehots,
                  const float* __restrict__ W,
                  const float* __restrict__ bias,
                  float* __restrict__ out_weight,   // [B, V]
                  float* __restrict__ out_kappa)    // [B, K]
{
    const int b    = blockIdx.x;
    const int tid  = threadIdx.x;
    const int warp = tid >> 5;
    const int lane = tid & 31;

    __shared__ float4 soh[2][CHUNK_F4];   // double-buffered onehots chunks (20KB)
    __shared__ float  sal[KMIX], sbe[KMIX], ska[KMIX];
    __shared__ float  sphi[TLEN];
    __shared__ float4 wpart[16 * 20];

    const float4* oh = (const float4*)(onehots + (size_t)b * TLEN * VDIM);
    const uint32_t s0_u32 = (uint32_t)__cvta_generic_to_shared(soh[0]);
    const uint32_t s1_u32 = (uint32_t)__cvta_generic_to_shared(soh[1]);

    // ---- fill the pipeline: chunks 0 and 1 in flight during the whole prologue
    {
        #pragma unroll
        for (int k = 0; k < CHUNK_F4 / NT; k++) {
            const int i = tid + k * NT;
            CP_ASYNC_16(s0_u32 + i * 16, oh + i);
        }
        CP_ASYNC_COMMIT();
        #pragma unroll
        for (int k = 0; k < CHUNK_F4 / NT; k++) {
            const int i = tid + k * NT;
            CP_ASYNC_16(s1_u32 + i * 16, oh + CHUNK_F4 + i);
        }
        CP_ASYNC_COMMIT();
    }

    // ---- mat-vec + transforms: warp w owns mixture component w ----
    {
        const float4* x4 = (const float4*)(x + (size_t)b * CELL);
        const float4* W4 = (const float4*)W;
        float s0 = 0.f, s1 = 0.f, s2 = 0.f;
        #pragma unroll 4
        for (int c4 = lane; c4 < CELL4; c4 += 32) {
            const float4 xv = x4[c4];
            const float4 w0 = W4[(warp)          * CELL4 + c4];
            const float4 w1 = W4[(warp + KMIX)   * CELL4 + c4];
            const float4 w2 = W4[(warp + 2*KMIX) * CELL4 + c4];
            s0 += xv.x * w0.x + xv.y * w0.y + xv.z * w0.z + xv.w * w0.w;
            s1 += xv.x * w1.x + xv.y * w1.y + xv.z * w1.z + xv.w * w1.w;
            s2 += xv.x * w2.x + xv.y * w2.y + xv.z * w2.z + xv.w * w2.w;
        }
        #pragma unroll
        for (int off = 16; off > 0; off >>= 1) {
            s0 += __shfl_xor_sync(0xffffffffu, s0, off);
            s1 += __shfl_xor_sync(0xffffffffu, s1, off);
            s2 += __shfl_xor_sync(0xffffffffu, s2, off);
        }
        if (lane == 0) {
            const float alpha = __expf(s0 + bias[warp]);
            const float beta  = __expf(s1 + bias[warp + KMIX]);
            const float kap   = kappa_old[(size_t)b * KMIX + warp]
                              + __expf(s2 + bias[warp + 2*KMIX]);
            sal[warp] = alpha;
            sbe[warp] = beta;
            ska[warp] = kap;
            out_kappa[(size_t)b * KMIX + warp] = kap;
        }
    }
    __syncthreads();

    // ---- phi[t] ----
    if (tid < TLEN) {
        const float u = (float)tid;
        float s = 0.0f;
        #pragma unroll
        for (int k = 0; k < KMIX; k++) {
            const float d = ska[k] - u;
            s += sal[k] * __expf(-sbe[k] * d * d);
        }
        sphi[tid] = s;
    }
    // (visibility of sphi is covered by the first pipeline __syncthreads below)

    // ---- streaming einsum through the cp.async pipeline ----
    const int c  = tid % 20;    // float4 column (v/4)
    const int t0 = tid / 20;    // 0..15

    float4 acc = make_float4(0.f, 0.f, 0.f, 0.f);
    #pragma unroll
    for (int q = 0; q < NCHUNK; q++) {
        if (q < NCHUNK - 1) { CP_ASYNC_WAIT_1(); } else { CP_ASYNC_WAIT_0(); }
        __syncthreads();                       // chunk q visible to all threads
        const float4* st = soh[q & 1];
        #pragma unroll
        for (int m = 0; m < CHUNK_ROWS / 16; m++) {
            const int rl = t0 + m * 16;        // row within chunk
            const float  p = sphi[q * CHUNK_ROWS + rl];
            const float4 o = st[rl * 20 + c];
            acc.x += p * o.x; acc.y += p * o.y; acc.z += p * o.z; acc.w += p * o.w;
        }
        __syncthreads();                       // all consumers done before refill
        if (q < NCHUNK - 2) {
            const uint32_t sdst = (q & 1) ? s1_u32 : s0_u32;
            const float4*  gsrc = oh + (q + 2) * CHUNK_F4;
            #pragma unroll
            for (int k = 0; k < CHUNK_F4 / NT; k++) {
                const int i = tid + k * NT;
                CP_ASYNC_16(sdst + i * 16, gsrc + i);
            }
            CP_ASYNC_COMMIT();
        }
    }

    wpart[t0 * 20 + c] = acc;
    __syncthreads();

    if (tid < VDIM) {
        const float* wp = (const float*)wpart;
        float s = 0.0f;
        #pragma unroll
        for (int j = 0; j < 16; j++) s += wp[j * VDIM + tid];
        out_weight[(size_t)b * VDIM + tid] = s;
    }
}

extern "C" void kernel_launch(void* const* d_in, const int* in_sizes, int n_in,
                              void* d_out, int out_size)
{
    const float* x         = (const float*)d_in[0];   // [B, CELL]
    const float* kappa_old = (const float*)d_in[1];   // [B, K]
    const float* onehots   = (const float*)d_in[2];   // [B, T, V]
    const float* W         = (const float*)d_in[3];   // [3K, CELL]
    const float* bias      = (const float*)d_in[4];   // [3K]

    float* out_weight = (float*)d_out;                        // [B, V]
    float* out_kappa  = (float*)d_out + (size_t)BATCH * VDIM; // [B, K]

    window_fused<<<BATCH, NT>>>(x, kappa_old, onehots, W, bias,
                                out_weight, out_kappa);
}